// round 2
// baseline (speedup 1.0000x reference)
#include <cuda_runtime.h>
#include <cstdint>

#define N_NODES 100000
#define N_EDGES 3200000
#define IN_DIM  256
#define OUT_DIM 128

// scratch for xw = x @ W  (51.2 MB, static device array — no allocations allowed)
__device__ float g_xw[(size_t)N_NODES * OUT_DIM];

// ---------------------------------------------------------------------------
// Kernel 1: zero the output (d_out is poisoned by the harness)
// ---------------------------------------------------------------------------
__global__ void zero_kernel(float* __restrict__ out) {
    size_t i = (size_t)blockIdx.x * blockDim.x + threadIdx.x;
    const size_t n4 = (size_t)N_NODES * OUT_DIM / 4;
    if (i < n4) {
        ((float4*)out)[i] = make_float4(0.f, 0.f, 0.f, 0.f);
    }
}

// ---------------------------------------------------------------------------
// Kernel 2: SGEMM  xw[M,128] = x[M,256] @ W[256,128]
// Classic smem-tiled register-blocked SGEMM. BM=128, BN=128, BK=16, 8x8/thread.
// ---------------------------------------------------------------------------
#define BM 128
#define BN 128
#define BK 16
#define TM 8
#define TN 8

__global__ __launch_bounds__(256) void gemm_kernel(const float* __restrict__ x,
                                                   const float* __restrict__ w) {
    __shared__ float As[BK][BM];
    __shared__ float Bs[BK][BN];

    const int tid = threadIdx.x;
    const int tx  = tid % 16;       // N direction
    const int ty  = tid / 16;       // M direction
    const int m0  = blockIdx.x * BM;

    float acc[TM][TN];
#pragma unroll
    for (int i = 0; i < TM; i++)
#pragma unroll
        for (int j = 0; j < TN; j++) acc[i][j] = 0.f;

    for (int k0 = 0; k0 < IN_DIM; k0 += BK) {
        // --- load A tile (128 rows x 16 cols), transposed into As[k][m]
#pragma unroll
        for (int it = 0; it < 2; it++) {
            int idx = tid + it * 256;      // 512 float4 slots
            int m   = idx >> 2;            // 0..127
            int kc  = idx & 3;             // which float4 along k
            int row = m0 + m;
            float4 v = make_float4(0.f, 0.f, 0.f, 0.f);
            if (row < N_NODES)
                v = *(const float4*)(x + (size_t)row * IN_DIM + k0 + kc * 4);
            As[kc * 4 + 0][m] = v.x;
            As[kc * 4 + 1][m] = v.y;
            As[kc * 4 + 2][m] = v.z;
            As[kc * 4 + 3][m] = v.w;
        }
        // --- load B tile (16 rows x 128 cols), natural layout
#pragma unroll
        for (int it = 0; it < 2; it++) {
            int idx = tid + it * 256;
            int k   = idx >> 5;            // 0..15
            int nc  = idx & 31;            // float4 along n
            float4 v = *(const float4*)(w + (size_t)(k0 + k) * OUT_DIM + nc * 4);
            *(float4*)&Bs[k][nc * 4] = v;
        }
        __syncthreads();

#pragma unroll
        for (int kk = 0; kk < BK; kk++) {
            float a[TM], b[TN];
#pragma unroll
            for (int i = 0; i < TM; i++) a[i] = As[kk][ty * TM + i];
#pragma unroll
            for (int j = 0; j < TN; j++) b[j] = Bs[kk][tx * TN + j];
#pragma unroll
            for (int i = 0; i < TM; i++)
#pragma unroll
                for (int j = 0; j < TN; j++) acc[i][j] += a[i] * b[j];
        }
        __syncthreads();
    }

    // --- store 8x8 tile (two float4 per row)
#pragma unroll
    for (int i = 0; i < TM; i++) {
        int row = m0 + ty * TM + i;
        if (row < N_NODES) {
            float* o = g_xw + (size_t)row * OUT_DIM + tx * TN;
            *(float4*)(o + 0) = make_float4(acc[i][0], acc[i][1], acc[i][2], acc[i][3]);
            *(float4*)(o + 4) = make_float4(acc[i][4], acc[i][5], acc[i][6], acc[i][7]);
        }
    }
}

// ---------------------------------------------------------------------------
// Kernel 3: edge scatter. One warp per edge: lane reads float4 of xw[src],
// scales by edge weight, vector-reduces into out[dst]. red.global.add.v4.f32
// (sm_90+) = no return trip, 1/4 the atomic op count of scalar atomicAdd.
// NOTE: edge indices are int32 (JAX x64 disabled downcasts jnp.int64 -> int32).
// ---------------------------------------------------------------------------
__global__ __launch_bounds__(256) void scatter_kernel(
    const int* __restrict__ esrc,
    const int* __restrict__ edst,
    const float* __restrict__ ew,
    float* __restrict__ out) {
    const int eidx = (int)(((size_t)blockIdx.x * blockDim.x + threadIdx.x) >> 5);
    const int lane = threadIdx.x & 31;
    if (eidx >= N_EDGES) return;

    const int   s = esrc[eidx];
    const int   d = edst[eidx];
    const float w = ew[eidx];

    float4 v = ((const float4*)(g_xw + (size_t)s * OUT_DIM))[lane];
    float* p = out + (size_t)d * OUT_DIM + lane * 4;

    asm volatile("red.global.add.v4.f32 [%0], {%1, %2, %3, %4};"
                 :: "l"(p), "f"(v.x * w), "f"(v.y * w), "f"(v.z * w), "f"(v.w * w)
                 : "memory");
}

// ---------------------------------------------------------------------------
// Kernel 4: in-place ReLU on the aggregated output
// ---------------------------------------------------------------------------
__global__ void relu_kernel(float* __restrict__ out) {
    size_t i = (size_t)blockIdx.x * blockDim.x + threadIdx.x;
    const size_t n4 = (size_t)N_NODES * OUT_DIM / 4;
    if (i < n4) {
        float4 v = ((float4*)out)[i];
        v.x = fmaxf(v.x, 0.f);
        v.y = fmaxf(v.y, 0.f);
        v.z = fmaxf(v.z, 0.f);
        v.w = fmaxf(v.w, 0.f);
        ((float4*)out)[i] = v;
    }
}

// ---------------------------------------------------------------------------
extern "C" void kernel_launch(void* const* d_in, const int* in_sizes, int n_in,
                              void* d_out, int out_size) {
    const float* x  = (const float*)d_in[0];       // [100000, 256] f32
    const float* w  = (const float*)d_in[1];       // [256, 128]    f32
    const float* ew = (const float*)d_in[2];       // [3.2M]        f32
    const int*   es = (const int*)d_in[3];         // [3.2M]        i32
    const int*   ed = (const int*)d_in[4];         // [3.2M]        i32
    float* out = (float*)d_out;                    // [100000, 128] f32

    const int n4       = N_NODES * OUT_DIM / 4;              // 3.2M float4
    const int zBlocks  = (n4 + 255) / 256;                   // 12500
    const int gBlocks  = (N_NODES + BM - 1) / BM;            // 782
    const long long sThreads = (long long)N_EDGES * 32;      // one warp/edge
    const int sBlocks  = (int)((sThreads + 255) / 256);      // 400000

    zero_kernel<<<zBlocks, 256>>>(out);
    gemm_kernel<<<gBlocks, 256>>>(x, w);
    scatter_kernel<<<sBlocks, 256>>>(es, ed, ew, out);
    relu_kernel<<<zBlocks, 256>>>(out);
}

// round 3
// speedup vs baseline: 1.1935x; 1.1935x over previous
#include <cuda_runtime.h>
#include <cstdint>

#define N_NODES 100000
#define N_EDGES 3200000
#define IN_DIM  256
#define OUT_DIM 128

// scratch for xw = x @ W  (51.2 MB, static device array — no allocations allowed)
__device__ float g_xw[(size_t)N_NODES * OUT_DIM];

// ---------------------------------------------------------------------------
// Kernel 1: zero the output (d_out is poisoned by the harness)
// ---------------------------------------------------------------------------
__global__ void zero_kernel(float* __restrict__ out) {
    size_t i = (size_t)blockIdx.x * blockDim.x + threadIdx.x;
    const size_t n4 = (size_t)N_NODES * OUT_DIM / 4;
    if (i < n4) {
        ((float4*)out)[i] = make_float4(0.f, 0.f, 0.f, 0.f);
    }
}

// ---------------------------------------------------------------------------
// Kernel 2: TF32 tensor-core GEMM  xw[M,128] = x[M,256] @ W[256,128]
// mma.sync.aligned.m16n8k8.row.col.f32.tf32.tf32.f32
// CTA: 256 thr = 8 warps (2 M x 4 N). BM=128, BN=128, BK=32. Warp: 64x32.
// Smem pads chosen for conflict-free fragment LDS (A pitch 36, B pitch 136).
// ---------------------------------------------------------------------------
#define BM 128
#define BK 32
#define A_PITCH 36
#define B_PITCH 136

__device__ __forceinline__ uint32_t f2tf32(float f) {
    uint32_t r;
    asm("cvt.rna.tf32.f32 %0, %1;" : "=r"(r) : "f"(f));
    return r;
}

__global__ __launch_bounds__(256) void gemm_tf32_kernel(const float* __restrict__ x,
                                                        const float* __restrict__ w) {
    __shared__ uint32_t As[BM * A_PITCH];    // [m][k], pitch 36 words
    __shared__ uint32_t Bs[BK * B_PITCH];    // [k][n], pitch 136 words

    const int tid    = threadIdx.x;
    const int wid    = tid >> 5;
    const int lane   = tid & 31;
    const int grp    = lane >> 2;            // 0..7
    const int qid    = lane & 3;             // 0..3
    const int warp_m = wid >> 2;             // 0..1
    const int warp_n = wid & 3;              // 0..3
    const int m0     = blockIdx.x * BM;
    const int m_base = warp_m * 64;
    const int n_base = warp_n * 32;

    float c[4][4][4];                        // [mt][nt][4]
#pragma unroll
    for (int mt = 0; mt < 4; mt++)
#pragma unroll
        for (int nt = 0; nt < 4; nt++)
#pragma unroll
            for (int r = 0; r < 4; r++) c[mt][nt][r] = 0.f;

    for (int k0 = 0; k0 < IN_DIM; k0 += BK) {
        // ---- load A tile: 128 rows x 32 k  (1024 float4 slots, 4/thread)
#pragma unroll
        for (int it = 0; it < 4; it++) {
            int s  = tid + it * 256;
            int m  = s >> 3;                 // 0..127
            int kc = s & 7;                  // float4 along k
            int row = m0 + m;
            float4 v = make_float4(0.f, 0.f, 0.f, 0.f);
            if (row < N_NODES)
                v = *(const float4*)(x + (size_t)row * IN_DIM + k0 + kc * 4);
            uint32_t* p = &As[m * A_PITCH + kc * 4];
            p[0] = f2tf32(v.x); p[1] = f2tf32(v.y);
            p[2] = f2tf32(v.z); p[3] = f2tf32(v.w);
        }
        // ---- load B tile: 32 k x 128 n
#pragma unroll
        for (int it = 0; it < 4; it++) {
            int s  = tid + it * 256;
            int k  = s >> 5;                 // 0..31
            int nc = s & 31;                 // float4 along n
            float4 v = *(const float4*)(w + (size_t)(k0 + k) * OUT_DIM + nc * 4);
            uint32_t* p = &Bs[k * B_PITCH + nc * 4];
            p[0] = f2tf32(v.x); p[1] = f2tf32(v.y);
            p[2] = f2tf32(v.z); p[3] = f2tf32(v.w);
        }
        __syncthreads();

#pragma unroll
        for (int ks = 0; ks < 4; ks++) {     // k-steps of 8 within BK
            const int kk = ks * 8;
            uint32_t a[4][4], b[4][2];
#pragma unroll
            for (int mt = 0; mt < 4; mt++) {
                int row = m_base + mt * 16 + grp;
                a[mt][0] = As[row * A_PITCH + kk + qid];
                a[mt][1] = As[(row + 8) * A_PITCH + kk + qid];
                a[mt][2] = As[row * A_PITCH + kk + qid + 4];
                a[mt][3] = As[(row + 8) * A_PITCH + kk + qid + 4];
            }
#pragma unroll
            for (int nt = 0; nt < 4; nt++) {
                int col = n_base + nt * 8 + grp;
                b[nt][0] = Bs[(kk + qid) * B_PITCH + col];
                b[nt][1] = Bs[(kk + qid + 4) * B_PITCH + col];
            }
#pragma unroll
            for (int mt = 0; mt < 4; mt++)
#pragma unroll
                for (int nt = 0; nt < 4; nt++) {
                    asm volatile(
                        "mma.sync.aligned.m16n8k8.row.col.f32.tf32.tf32.f32 "
                        "{%0,%1,%2,%3}, {%4,%5,%6,%7}, {%8,%9}, {%0,%1,%2,%3};\n"
                        : "+f"(c[mt][nt][0]), "+f"(c[mt][nt][1]),
                          "+f"(c[mt][nt][2]), "+f"(c[mt][nt][3])
                        : "r"(a[mt][0]), "r"(a[mt][1]), "r"(a[mt][2]), "r"(a[mt][3]),
                          "r"(b[nt][0]), "r"(b[nt][1]));
                }
        }
        __syncthreads();
    }

    // ---- epilogue: c[mt][nt] -> g_xw. Per tile, lane owns rows grp, grp+8;
    // cols 2*qid, 2*qid+1 -> one float2 per row.
#pragma unroll
    for (int mt = 0; mt < 4; mt++) {
        int r0 = m0 + m_base + mt * 16 + grp;
        int r1 = r0 + 8;
#pragma unroll
        for (int nt = 0; nt < 4; nt++) {
            int col = n_base + nt * 8 + qid * 2;
            if (r0 < N_NODES)
                *(float2*)(g_xw + (size_t)r0 * OUT_DIM + col) =
                    make_float2(c[mt][nt][0], c[mt][nt][1]);
            if (r1 < N_NODES)
                *(float2*)(g_xw + (size_t)r1 * OUT_DIM + col) =
                    make_float2(c[mt][nt][2], c[mt][nt][3]);
        }
    }
}

// ---------------------------------------------------------------------------
// Kernel 3: edge scatter. One warp per edge: lane reads float4 of xw[src],
// scales by edge weight, vector-reduces into out[dst]. red.global.add.v4.f32
// (sm_90+) = no return trip, 1/4 the atomic op count of scalar atomicAdd.
// ---------------------------------------------------------------------------
__global__ __launch_bounds__(256) void scatter_kernel(
    const int* __restrict__ esrc,
    const int* __restrict__ edst,
    const float* __restrict__ ew,
    float* __restrict__ out) {
    const int eidx = (int)(((size_t)blockIdx.x * blockDim.x + threadIdx.x) >> 5);
    const int lane = threadIdx.x & 31;
    if (eidx >= N_EDGES) return;

    const int   s = esrc[eidx];
    const int   d = edst[eidx];
    const float w = ew[eidx];

    float4 v = ((const float4*)(g_xw + (size_t)s * OUT_DIM))[lane];
    float* p = out + (size_t)d * OUT_DIM + lane * 4;

    asm volatile("red.global.add.v4.f32 [%0], {%1, %2, %3, %4};"
                 :: "l"(p), "f"(v.x * w), "f"(v.y * w), "f"(v.z * w), "f"(v.w * w)
                 : "memory");
}

// ---------------------------------------------------------------------------
// Kernel 4: in-place ReLU on the aggregated output
// ---------------------------------------------------------------------------
__global__ void relu_kernel(float* __restrict__ out) {
    size_t i = (size_t)blockIdx.x * blockDim.x + threadIdx.x;
    const size_t n4 = (size_t)N_NODES * OUT_DIM / 4;
    if (i < n4) {
        float4 v = ((float4*)out)[i];
        v.x = fmaxf(v.x, 0.f);
        v.y = fmaxf(v.y, 0.f);
        v.z = fmaxf(v.z, 0.f);
        v.w = fmaxf(v.w, 0.f);
        ((float4*)out)[i] = v;
    }
}

// ---------------------------------------------------------------------------
extern "C" void kernel_launch(void* const* d_in, const int* in_sizes, int n_in,
                              void* d_out, int out_size) {
    const float* x  = (const float*)d_in[0];       // [100000, 256] f32
    const float* w  = (const float*)d_in[1];       // [256, 128]    f32
    const float* ew = (const float*)d_in[2];       // [3.2M]        f32
    const int*   es = (const int*)d_in[3];         // [3.2M]        i32
    const int*   ed = (const int*)d_in[4];         // [3.2M]        i32
    float* out = (float*)d_out;                    // [100000, 128] f32

    const int n4       = N_NODES * OUT_DIM / 4;              // 3.2M float4
    const int zBlocks  = (n4 + 255) / 256;                   // 12500
    const int gBlocks  = (N_NODES + BM - 1) / BM;            // 782
    const long long sThreads = (long long)N_EDGES * 32;      // one warp/edge
    const int sBlocks  = (int)((sThreads + 255) / 256);      // 400000

    zero_kernel<<<zBlocks, 256>>>(out);
    gemm_tf32_kernel<<<gBlocks, 256>>>(x, w);
    scatter_kernel<<<sBlocks, 256>>>(es, ed, ew, out);
    relu_kernel<<<zBlocks, 256>>>(out);
}

// round 4
// speedup vs baseline: 2.3623x; 1.9793x over previous
#include <cuda_runtime.h>
#include <cstdint>

#define N_NODES 100000
#define N_EDGES 3200000
#define IN_DIM  256
#define OUT_DIM 128

// ---------------- static scratch (no allocations allowed) ------------------
__device__ float g_xw[(size_t)N_NODES * OUT_DIM];   // 51.2 MB  x @ W
__device__ int   g_bsrc[N_EDGES];                   // 12.8 MB  bucketed src
__device__ float g_bw[N_EDGES];                     // 12.8 MB  bucketed weight
__device__ int   g_count[N_NODES];                  // per-dst degree
__device__ int   g_scan[N_NODES];                   // block-local exclusive scan
__device__ int   g_off[N_NODES + 1];                // CSR row offsets
__device__ int   g_fill[N_NODES];                   // fill cursors
__device__ int   g_bsum[128];                       // per-block sums
__device__ int   g_bbase[128];                      // scanned block bases

#define SCAN_B 1024
#define SCAN_NBLK 98                                // ceil(100000/1024)

// ---------------------------------------------------------------------------
// TF32 tensor-core GEMM  xw[M,128] = x[M,256] @ W[256,128]   (unchanged)
// ---------------------------------------------------------------------------
#define BM 128
#define BK 32
#define A_PITCH 36
#define B_PITCH 136

__device__ __forceinline__ uint32_t f2tf32(float f) {
    uint32_t r;
    asm("cvt.rna.tf32.f32 %0, %1;" : "=r"(r) : "f"(f));
    return r;
}

__global__ __launch_bounds__(256) void gemm_tf32_kernel(const float* __restrict__ x,
                                                        const float* __restrict__ w) {
    __shared__ uint32_t As[BM * A_PITCH];
    __shared__ uint32_t Bs[BK * B_PITCH];

    const int tid    = threadIdx.x;
    const int wid    = tid >> 5;
    const int lane   = tid & 31;
    const int grp    = lane >> 2;
    const int qid    = lane & 3;
    const int warp_m = wid >> 2;
    const int warp_n = wid & 3;
    const int m0     = blockIdx.x * BM;
    const int m_base = warp_m * 64;
    const int n_base = warp_n * 32;

    float c[4][4][4];
#pragma unroll
    for (int mt = 0; mt < 4; mt++)
#pragma unroll
        for (int nt = 0; nt < 4; nt++)
#pragma unroll
            for (int r = 0; r < 4; r++) c[mt][nt][r] = 0.f;

    for (int k0 = 0; k0 < IN_DIM; k0 += BK) {
#pragma unroll
        for (int it = 0; it < 4; it++) {
            int s  = tid + it * 256;
            int m  = s >> 3;
            int kc = s & 7;
            int row = m0 + m;
            float4 v = make_float4(0.f, 0.f, 0.f, 0.f);
            if (row < N_NODES)
                v = *(const float4*)(x + (size_t)row * IN_DIM + k0 + kc * 4);
            uint32_t* p = &As[m * A_PITCH + kc * 4];
            p[0] = f2tf32(v.x); p[1] = f2tf32(v.y);
            p[2] = f2tf32(v.z); p[3] = f2tf32(v.w);
        }
#pragma unroll
        for (int it = 0; it < 4; it++) {
            int s  = tid + it * 256;
            int k  = s >> 5;
            int nc = s & 31;
            float4 v = *(const float4*)(w + (size_t)(k0 + k) * OUT_DIM + nc * 4);
            uint32_t* p = &Bs[k * B_PITCH + nc * 4];
            p[0] = f2tf32(v.x); p[1] = f2tf32(v.y);
            p[2] = f2tf32(v.z); p[3] = f2tf32(v.w);
        }
        __syncthreads();

#pragma unroll
        for (int ks = 0; ks < 4; ks++) {
            const int kk = ks * 8;
            uint32_t a[4][4], b[4][2];
#pragma unroll
            for (int mt = 0; mt < 4; mt++) {
                int row = m_base + mt * 16 + grp;
                a[mt][0] = As[row * A_PITCH + kk + qid];
                a[mt][1] = As[(row + 8) * A_PITCH + kk + qid];
                a[mt][2] = As[row * A_PITCH + kk + qid + 4];
                a[mt][3] = As[(row + 8) * A_PITCH + kk + qid + 4];
            }
#pragma unroll
            for (int nt = 0; nt < 4; nt++) {
                int col = n_base + nt * 8 + grp;
                b[nt][0] = Bs[(kk + qid) * B_PITCH + col];
                b[nt][1] = Bs[(kk + qid + 4) * B_PITCH + col];
            }
#pragma unroll
            for (int mt = 0; mt < 4; mt++)
#pragma unroll
                for (int nt = 0; nt < 4; nt++) {
                    asm volatile(
                        "mma.sync.aligned.m16n8k8.row.col.f32.tf32.tf32.f32 "
                        "{%0,%1,%2,%3}, {%4,%5,%6,%7}, {%8,%9}, {%0,%1,%2,%3};\n"
                        : "+f"(c[mt][nt][0]), "+f"(c[mt][nt][1]),
                          "+f"(c[mt][nt][2]), "+f"(c[mt][nt][3])
                        : "r"(a[mt][0]), "r"(a[mt][1]), "r"(a[mt][2]), "r"(a[mt][3]),
                          "r"(b[nt][0]), "r"(b[nt][1]));
                }
        }
        __syncthreads();
    }

#pragma unroll
    for (int mt = 0; mt < 4; mt++) {
        int r0 = m0 + m_base + mt * 16 + grp;
        int r1 = r0 + 8;
#pragma unroll
        for (int nt = 0; nt < 4; nt++) {
            int col = n_base + nt * 8 + qid * 2;
            if (r0 < N_NODES)
                *(float2*)(g_xw + (size_t)r0 * OUT_DIM + col) =
                    make_float2(c[mt][nt][0], c[mt][nt][1]);
            if (r1 < N_NODES)
                *(float2*)(g_xw + (size_t)r1 * OUT_DIM + col) =
                    make_float2(c[mt][nt][2], c[mt][nt][3]);
        }
    }
}

// ---------------------------------------------------------------------------
// CSR build: zero counts -> histogram -> scan (3 stages) -> fill buckets
// ---------------------------------------------------------------------------
__global__ void zcount_kernel() {
    int i = blockIdx.x * blockDim.x + threadIdx.x;
    if (i < N_NODES) g_count[i] = 0;
}

__global__ void hist_kernel(const int* __restrict__ edst) {
    int e = blockIdx.x * blockDim.x + threadIdx.x;
    if (e < N_EDGES) atomicAdd(&g_count[edst[e]], 1);
}

__global__ __launch_bounds__(SCAN_B) void scan1_kernel() {
    __shared__ int s[SCAN_B];
    int tid = threadIdx.x;
    int i   = blockIdx.x * SCAN_B + tid;
    int v   = (i < N_NODES) ? g_count[i] : 0;
    s[tid] = v;
    __syncthreads();
#pragma unroll
    for (int off = 1; off < SCAN_B; off <<= 1) {
        int t = (tid >= off) ? s[tid - off] : 0;
        __syncthreads();
        s[tid] += t;
        __syncthreads();
    }
    if (i < N_NODES) g_scan[i] = s[tid] - v;       // exclusive within block
    if (tid == SCAN_B - 1) g_bsum[blockIdx.x] = s[tid];
}

__global__ __launch_bounds__(128) void scan2_kernel() {
    __shared__ int s[128];
    int tid = threadIdx.x;
    int v   = (tid < SCAN_NBLK) ? g_bsum[tid] : 0;
    s[tid] = v;
    __syncthreads();
#pragma unroll
    for (int off = 1; off < 128; off <<= 1) {
        int t = (tid >= off) ? s[tid - off] : 0;
        __syncthreads();
        s[tid] += t;
        __syncthreads();
    }
    if (tid < SCAN_NBLK) g_bbase[tid] = s[tid] - v; // exclusive
}

__global__ __launch_bounds__(SCAN_B) void scan3_kernel() {
    int i = blockIdx.x * SCAN_B + threadIdx.x;
    if (i < N_NODES) {
        int o = g_scan[i] + g_bbase[blockIdx.x];
        g_off[i]  = o;
        g_fill[i] = o;
    }
    if (i == 0) g_off[N_NODES] = N_EDGES;
}

__global__ void fill_kernel(const int* __restrict__ esrc,
                            const int* __restrict__ edst,
                            const float* __restrict__ ew) {
    int e = blockIdx.x * blockDim.x + threadIdx.x;
    if (e < N_EDGES) {
        int d   = edst[e];
        int pos = atomicAdd(&g_fill[d], 1);
        g_bsrc[pos] = esrc[e];
        g_bw[pos]   = ew[e];
    }
}

// ---------------------------------------------------------------------------
// Aggregate: one warp per dst node. Lanes cooperatively load 32 edge records
// (coalesced), shfl-broadcast each, gather xw[src] float4/lane, accumulate in
// registers. Single write per out row with fused ReLU. No atomics.
// ---------------------------------------------------------------------------
__global__ __launch_bounds__(256) void gather_kernel(float* __restrict__ out) {
    const int node = blockIdx.x * 8 + (threadIdx.x >> 5);
    const int lane = threadIdx.x & 31;
    if (node >= N_NODES) return;

    const int beg = g_off[node];
    const int end = g_off[node + 1];

    float4 acc = make_float4(0.f, 0.f, 0.f, 0.f);

    for (int base = beg; base < end; base += 32) {
        const int n = min(32, end - base);
        int   mysrc = 0;
        float myw   = 0.f;
        if (lane < n) {
            mysrc = g_bsrc[base + lane];
            myw   = g_bw[base + lane];
        }
        for (int j = 0; j < n; j++) {
            const int   src = __shfl_sync(0xffffffff, mysrc, j);
            const float w   = __shfl_sync(0xffffffff, myw, j);
            const float4 v = ((const float4*)(g_xw + (size_t)src * OUT_DIM))[lane];
            acc.x += w * v.x;
            acc.y += w * v.y;
            acc.z += w * v.z;
            acc.w += w * v.w;
        }
    }

    acc.x = fmaxf(acc.x, 0.f);
    acc.y = fmaxf(acc.y, 0.f);
    acc.z = fmaxf(acc.z, 0.f);
    acc.w = fmaxf(acc.w, 0.f);
    ((float4*)(out + (size_t)node * OUT_DIM))[lane] = acc;
}

// ---------------------------------------------------------------------------
extern "C" void kernel_launch(void* const* d_in, const int* in_sizes, int n_in,
                              void* d_out, int out_size) {
    const float* x  = (const float*)d_in[0];       // [100000, 256] f32
    const float* w  = (const float*)d_in[1];       // [256, 128]    f32
    const float* ew = (const float*)d_in[2];       // [3.2M]        f32
    const int*   es = (const int*)d_in[3];         // [3.2M]        i32
    const int*   ed = (const int*)d_in[4];         // [3.2M]        i32
    float* out = (float*)d_out;                    // [100000, 128] f32

    const int eBlocks = (N_EDGES + 255) / 256;     // 12500
    const int nBlocks = (N_NODES + 255) / 256;     // 391
    const int gBlocks = (N_NODES + BM - 1) / BM;   // 782
    const int aBlocks = (N_NODES + 7) / 8;         // 12500 (8 warps/block)

    zcount_kernel<<<nBlocks, 256>>>();
    gemm_tf32_kernel<<<gBlocks, 256>>>(x, w);
    hist_kernel<<<eBlocks, 256>>>(ed);
    scan1_kernel<<<SCAN_NBLK, SCAN_B>>>();
    scan2_kernel<<<1, 128>>>();
    scan3_kernel<<<SCAN_NBLK, SCAN_B>>>();
    fill_kernel<<<eBlocks, 256>>>(es, ed, ew);
    gather_kernel<<<aBlocks, 256>>>(out);
}

// round 6
// speedup vs baseline: 3.0087x; 1.2736x over previous
#include <cuda_runtime.h>
#include <cuda_fp16.h>
#include <cstdint>

#define N_NODES 100000
#define N_EDGES 3200000
#define IN_DIM  256
#define OUT_DIM 128

// ---------------- static scratch (no allocations allowed) ------------------
__device__ __half g_xw[(size_t)N_NODES * OUT_DIM]; // 25.6 MB  x @ W (fp16)
__device__ int2   g_bucket[N_EDGES];               // 25.6 MB  {src, w bits}
__device__ int    g_count[N_NODES];                // per-dst degree
__device__ int    g_scan[N_NODES];                 // block-local exclusive scan
__device__ int    g_off[N_NODES + 1];              // CSR row offsets
__device__ int    g_fill[N_NODES];                 // fill cursors
__device__ int    g_bsum[128];                     // per-block sums
__device__ int    g_bbase[128];                    // scanned block bases

#define SCAN_B 1024
#define SCAN_NBLK 98                               // ceil(100000/1024)

// ---------------------------------------------------------------------------
// TF32 tensor-core GEMM  xw[M,128] = x[M,256] @ W[256,128], fp16 output
// ---------------------------------------------------------------------------
#define BM 128
#define BK 32
#define A_PITCH 36
#define B_PITCH 136

__device__ __forceinline__ uint32_t f2tf32(float f) {
    uint32_t r;
    asm("cvt.rna.tf32.f32 %0, %1;" : "=r"(r) : "f"(f));
    return r;
}

__global__ __launch_bounds__(256) void gemm_tf32_kernel(const float* __restrict__ x,
                                                        const float* __restrict__ w) {
    __shared__ uint32_t As[BM * A_PITCH];
    __shared__ uint32_t Bs[BK * B_PITCH];

    const int tid    = threadIdx.x;
    const int wid    = tid >> 5;
    const int lane   = tid & 31;
    const int grp    = lane >> 2;
    const int qid    = lane & 3;
    const int warp_m = wid >> 2;
    const int warp_n = wid & 3;
    const int m0     = blockIdx.x * BM;
    const int m_base = warp_m * 64;
    const int n_base = warp_n * 32;

    float c[4][4][4];
#pragma unroll
    for (int mt = 0; mt < 4; mt++)
#pragma unroll
        for (int nt = 0; nt < 4; nt++)
#pragma unroll
            for (int r = 0; r < 4; r++) c[mt][nt][r] = 0.f;

    for (int k0 = 0; k0 < IN_DIM; k0 += BK) {
#pragma unroll
        for (int it = 0; it < 4; it++) {
            int s  = tid + it * 256;
            int m  = s >> 3;
            int kc = s & 7;
            int row = m0 + m;
            float4 v = make_float4(0.f, 0.f, 0.f, 0.f);
            if (row < N_NODES)
                v = *(const float4*)(x + (size_t)row * IN_DIM + k0 + kc * 4);
            uint32_t* p = &As[m * A_PITCH + kc * 4];
            p[0] = f2tf32(v.x); p[1] = f2tf32(v.y);
            p[2] = f2tf32(v.z); p[3] = f2tf32(v.w);
        }
#pragma unroll
        for (int it = 0; it < 4; it++) {
            int s  = tid + it * 256;
            int k  = s >> 5;
            int nc = s & 31;
            float4 v = *(const float4*)(w + (size_t)(k0 + k) * OUT_DIM + nc * 4);
            uint32_t* p = &Bs[k * B_PITCH + nc * 4];
            p[0] = f2tf32(v.x); p[1] = f2tf32(v.y);
            p[2] = f2tf32(v.z); p[3] = f2tf32(v.w);
        }
        __syncthreads();

#pragma unroll
        for (int ks = 0; ks < 4; ks++) {
            const int kk = ks * 8;
            uint32_t a[4][4], b[4][2];
#pragma unroll
            for (int mt = 0; mt < 4; mt++) {
                int row = m_base + mt * 16 + grp;
                a[mt][0] = As[row * A_PITCH + kk + qid];
                a[mt][1] = As[(row + 8) * A_PITCH + kk + qid];
                a[mt][2] = As[row * A_PITCH + kk + qid + 4];
                a[mt][3] = As[(row + 8) * A_PITCH + kk + qid + 4];
            }
#pragma unroll
            for (int nt = 0; nt < 4; nt++) {
                int col = n_base + nt * 8 + grp;
                b[nt][0] = Bs[(kk + qid) * B_PITCH + col];
                b[nt][1] = Bs[(kk + qid + 4) * B_PITCH + col];
            }
#pragma unroll
            for (int mt = 0; mt < 4; mt++)
#pragma unroll
                for (int nt = 0; nt < 4; nt++) {
                    asm volatile(
                        "mma.sync.aligned.m16n8k8.row.col.f32.tf32.tf32.f32 "
                        "{%0,%1,%2,%3}, {%4,%5,%6,%7}, {%8,%9}, {%0,%1,%2,%3};\n"
                        : "+f"(c[mt][nt][0]), "+f"(c[mt][nt][1]),
                          "+f"(c[mt][nt][2]), "+f"(c[mt][nt][3])
                        : "r"(a[mt][0]), "r"(a[mt][1]), "r"(a[mt][2]), "r"(a[mt][3]),
                          "r"(b[nt][0]), "r"(b[nt][1]));
                }
        }
        __syncthreads();
    }

    // epilogue: convert to fp16, one half2 (4B) per row per tile
#pragma unroll
    for (int mt = 0; mt < 4; mt++) {
        int r0 = m0 + m_base + mt * 16 + grp;
        int r1 = r0 + 8;
#pragma unroll
        for (int nt = 0; nt < 4; nt++) {
            int col = n_base + nt * 8 + qid * 2;
            if (r0 < N_NODES)
                *(__half2*)(g_xw + (size_t)r0 * OUT_DIM + col) =
                    __floats2half2_rn(c[mt][nt][0], c[mt][nt][1]);
            if (r1 < N_NODES)
                *(__half2*)(g_xw + (size_t)r1 * OUT_DIM + col) =
                    __floats2half2_rn(c[mt][nt][2], c[mt][nt][3]);
        }
    }
}

// ---------------------------------------------------------------------------
// CSR build: zero counts -> histogram -> scan (3 stages) -> fill buckets
// ---------------------------------------------------------------------------
__global__ void zcount_kernel() {
    int i = blockIdx.x * blockDim.x + threadIdx.x;
    if (i < N_NODES) g_count[i] = 0;
}

__global__ void hist_kernel(const int* __restrict__ edst) {
    int e = blockIdx.x * blockDim.x + threadIdx.x;
    if (e < N_EDGES) atomicAdd(&g_count[edst[e]], 1);
}

__global__ __launch_bounds__(SCAN_B) void scan1_kernel() {
    __shared__ int s[SCAN_B];
    int tid = threadIdx.x;
    int i   = blockIdx.x * SCAN_B + tid;
    int v   = (i < N_NODES) ? g_count[i] : 0;
    s[tid] = v;
    __syncthreads();
#pragma unroll
    for (int off = 1; off < SCAN_B; off <<= 1) {
        int t = (tid >= off) ? s[tid - off] : 0;
        __syncthreads();
        s[tid] += t;
        __syncthreads();
    }
    if (i < N_NODES) g_scan[i] = s[tid] - v;       // exclusive within block
    if (tid == SCAN_B - 1) g_bsum[blockIdx.x] = s[tid];
}

__global__ __launch_bounds__(128) void scan2_kernel() {
    __shared__ int s[128];
    int tid = threadIdx.x;
    int v   = (tid < SCAN_NBLK) ? g_bsum[tid] : 0;
    s[tid] = v;
    __syncthreads();
#pragma unroll
    for (int off = 1; off < 128; off <<= 1) {
        int t = (tid >= off) ? s[tid - off] : 0;
        __syncthreads();
        s[tid] += t;
        __syncthreads();
    }
    if (tid < SCAN_NBLK) g_bbase[tid] = s[tid] - v; // exclusive
}

__global__ __launch_bounds__(SCAN_B) void scan3_kernel() {
    int i = blockIdx.x * SCAN_B + threadIdx.x;
    if (i < N_NODES) {
        int o = g_scan[i] + g_bbase[blockIdx.x];
        g_off[i]  = o;
        g_fill[i] = o;
    }
    if (i == 0) g_off[N_NODES] = N_EDGES;
}

__global__ void fill_kernel(const int* __restrict__ esrc,
                            const int* __restrict__ edst,
                            const float* __restrict__ ew) {
    int e = blockIdx.x * blockDim.x + threadIdx.x;
    if (e < N_EDGES) {
        int d   = edst[e];
        int pos = atomicAdd(&g_fill[d], 1);
        g_bucket[pos] = make_int2(esrc[e], __float_as_int(ew[e]));
    }
}

// ---------------------------------------------------------------------------
// Aggregate: one warp per dst node. Lanes cooperatively load 32 packed edge
// records (coalesced int2), shfl-broadcast each, gather 4 fp16 of xw[src] per
// lane (8B), fp32-accumulate. Single fused-ReLU write per out row. No atomics.
// ---------------------------------------------------------------------------
__global__ __launch_bounds__(256) void gather_kernel(float* __restrict__ out) {
    const int node = blockIdx.x * 8 + (threadIdx.x >> 5);
    const int lane = threadIdx.x & 31;
    if (node >= N_NODES) return;

    const int beg = g_off[node];
    const int end = g_off[node + 1];

    float4 acc = make_float4(0.f, 0.f, 0.f, 0.f);

    for (int base = beg; base < end; base += 32) {
        const int n = min(32, end - base);
        int   mysrc = 0;
        float myw   = 0.f;
        if (lane < n) {
            int2 rec = g_bucket[base + lane];
            mysrc = rec.x;
            myw   = __int_as_float(rec.y);
        }
        for (int j = 0; j < n; j++) {
            const int   src = __shfl_sync(0xffffffff, mysrc, j);
            const float w   = __shfl_sync(0xffffffff, myw, j);
            // 4 halves per lane: one 8-byte load
            const __half2* row = (const __half2*)(g_xw + (size_t)src * OUT_DIM);
            float2 v0 = __half22float2(row[lane * 2 + 0]);
            float2 v1 = __half22float2(row[lane * 2 + 1]);
            acc.x += w * v0.x;
            acc.y += w * v0.y;
            acc.z += w * v1.x;
            acc.w += w * v1.y;
        }
    }

    acc.x = fmaxf(acc.x, 0.f);
    acc.y = fmaxf(acc.y, 0.f);
    acc.z = fmaxf(acc.z, 0.f);
    acc.w = fmaxf(acc.w, 0.f);
    ((float4*)(out + (size_t)node * OUT_DIM))[lane] = acc;
}

// ---------------------------------------------------------------------------
extern "C" void kernel_launch(void* const* d_in, const int* in_sizes, int n_in,
                              void* d_out, int out_size) {
    const float* x  = (const float*)d_in[0];       // [100000, 256] f32
    const float* w  = (const float*)d_in[1];       // [256, 128]    f32
    const float* ew = (const float*)d_in[2];       // [3.2M]        f32
    const int*   es = (const int*)d_in[3];         // [3.2M]        i32
    const int*   ed = (const int*)d_in[4];         // [3.2M]        i32
    float* out = (float*)d_out;                    // [100000, 128] f32

    const int eBlocks = (N_EDGES + 255) / 256;     // 12500
    const int nBlocks = (N_NODES + 255) / 256;     // 391
    const int gBlocks = (N_NODES + BM - 1) / BM;   // 782
    const int aBlocks = (N_NODES + 7) / 8;         // 12500 (8 warps/block)

    // static side stream + events for GEMM || CSR-build overlap
    // (host-side objects only; created once — no device memory involved)
    static cudaStream_t side = nullptr;
    static cudaEvent_t  evFork = nullptr, evJoin = nullptr;
    if (!side) {
        cudaStreamCreateWithFlags(&side, cudaStreamNonBlocking);
        cudaEventCreateWithFlags(&evFork, cudaEventDisableTiming);
        cudaEventCreateWithFlags(&evJoin, cudaEventDisableTiming);
    }

    // fork: GEMM on side stream
    cudaEventRecord(evFork, 0);
    cudaStreamWaitEvent(side, evFork, 0);
    gemm_tf32_kernel<<<gBlocks, 256, 0, side>>>(x, w);
    cudaEventRecord(evJoin, side);

    // CSR build on main stream (independent of GEMM)
    zcount_kernel<<<nBlocks, 256>>>();
    hist_kernel<<<eBlocks, 256>>>(ed);
    scan1_kernel<<<SCAN_NBLK, SCAN_B>>>();
    scan2_kernel<<<1, 128>>>();
    scan3_kernel<<<SCAN_NBLK, SCAN_B>>>();
    fill_kernel<<<eBlocks, 256>>>(es, ed, ew);

    // join: gather needs both g_xw (side) and buckets (main)
    cudaStreamWaitEvent(0, evJoin, 0);
    gather_kernel<<<aBlocks, 256>>>(out);
}